// round 9
// baseline (speedup 1.0000x reference)
#include <cuda_runtime.h>
#include <math.h>

#define P_L1 20
#define P_R1 70
#define P_L2 120
#define P_R2 170
#define NFACT 10
#define TT 200
#define NTRIALS 256
#define NCONFIGS 128
#define TWN 50
#define WIN 53                        // softplus window [L-1, R+1]
#define PLANE (NTRIALS * NCONFIGS)    // 32768

#define N_FILL 4000                   // 1000 planes * 4 quarter-planes
#define N_WARP 2560                   // 20 k * 128 trial-pairs
#define GRP 13                        // 8 fill + 5 warp per group
#define NGRP 512                      // 4096 fill slots (4000 valid), 2560 warp exact

// JAX softplus: max(x,0) + log1p(exp(-|x|))
__device__ __forceinline__ float softplus_f(float x) {
    return fmaxf(x, 0.0f) + log1pf(expf(-fabsf(x)));
}

__global__ void __launch_bounds__(256) fused_kernel(
    const float* __restrict__ beta,
    const float* __restrict__ toff,    // [256,128,20]
    const float* __restrict__ coff,    // [128,20]
    const float* __restrict__ timev,   // [200]
    float* __restrict__ out)
{
    const int bid = blockIdx.x;
    const int grp = bid / GRP;
    const int sub = bid - grp * GRP;

    if (sub < 8) {
        // ---------------- fill path: quarter-plane broadcast ----------------
        int fid = grp * 8 + sub;           // 0..4095, valid 0..3999
        if (fid >= N_FILL) return;
        int p    = fid >> 2;               // plane 0..999 = (l, static col j)
        int quad = fid & 3;
        int l = p / 100;
        int j = p - l * 100;
        int t = (j < P_L1) ? j : ((j < 70) ? j + 50 : j + 100);

        float v = softplus_f(beta[l * TT + t]);
        float4 v4 = make_float4(v, v, v, v);

        float4* op = (float4*)(out + (size_t)(l * TT + t) * PLANE)
                   + quad * (PLANE / 16);
        #pragma unroll 4
        for (int i = threadIdx.x; i < PLANE / 16; i += 256)  // 2048 float4
            __stcs(&op[i], v4);
        return;
    }

    // ------------------- warp path: one (k, trial-pair) per block ---------
    const int wid = grp * 5 + (sub - 8);   // 0..2559
    const int k   = wid >> 7;              // 0..19 (seg*10 + l)
    const int np  = wid & 127;             // trial pair
    const int seg = (k >= NFACT) ? 1 : 0;
    const int l   = k - seg * NFACT;
    const int Ls  = seg ? P_L2 : P_L1;
    const int Rs  = seg ? P_R2 : P_R1;

    const int tid  = threadIdx.x;
    const int lane = tid & 31;
    const int w    = tid >> 5;             // warp 0..7
    const int n    = np * 2 + (w >> 2);    // trial (warps 0-3: n0, 4-7: n0+1)
    const int q    = w & 3;                // tw phase 0..3
    const int c0   = lane * 4;             // 4 consecutive configs per thread

    __shared__ float sf[WIN];

    if (tid < WIN)
        sf[tid] = softplus_f(beta[l * TT + (Ls - 1) + tid]);
    __syncthreads();

    // warp-parallel first-max argmax over sf[1..50] (each warp redundantly)
    float peak;
    {
        float bv = sf[1 + lane];
        int   bi = lane;                   // lanes cover elems 0..31
        if (lane < 18) {                   // elems 32..49
            float v2 = sf[33 + lane];
            if (v2 > bv) { bv = v2; bi = lane + 32; }
        }
        #pragma unroll
        for (int off = 16; off > 0; off >>= 1) {
            float ov = __shfl_xor_sync(0xffffffffu, bv, off);
            int   oi = __shfl_xor_sync(0xffffffffu, bi, off);
            if (ov > bv || (ov == bv && oi < bi)) { bv = ov; bi = oi; }
        }
        peak = timev[Ls + bi];
    }

    const float dt    = timev[1] - timev[0];
    const float rdt   = 1.0f / dt;
    const float ll    = timev[Ls];
    const float rl    = timev[Rs];
    const float shift = (float)(Ls - 1);
    const float b1s   = ll * rdt - shift;  // shifted left-branch intercept

    // per-config warp params (index-space affine pieces, pre-shifted)
    float t0[4], a1[4], a2[4], b2s[4];
    #pragma unroll
    for (int j = 0; j < 4; ++j) {
        int c = c0 + j;
        float s = peak + toff[(n * NCONFIGS + c) * (2 * NFACT) + k]
                       + coff[c * (2 * NFACT) + k];
        if (s <= ll) s = ll + dt;
        if (s >= rl) s = rl - dt;
        float lsp    = s - ll;
        float lslope = (peak - ll) / lsp;
        float rslope = (peak - rl) / (s - rl);
        t0[j]  = lsp * rdt;                         // branch point in tw units
        a1[j]  = lslope;
        a2[j]  = rslope;
        b2s[j] = (peak - lsp * rslope) * rdt - shift;
    }

    // base float4 pointer at (l, Ls, n, c0)
    float4* op = (float4*)(out + ((size_t)(l * TT + Ls) * NTRIALS + n) * NCONFIGS + c0);

    #pragma unroll 1
    for (int tw = q; tw < TWN; tw += 4) {
        float twf = (float)tw;
        float4 v;
        float* vp = (float*)&v;
        #pragma unroll
        for (int j = 0; j < 4; ++j) {
            // shifted index-space warp: wis = wi - (Ls-1), exact in fp32
            float wis = (twf < t0[j]) ? fmaf(twf, a1[j], b1s)
                                      : fmaf(twf, a2[j], b2s[j]);
            float fl = floorf(wis);
            float cw = wis - fl;
            int idx = (int)fl;             // proven 0 <= idx <= 51
            float f0 = sf[idx];
            float f1 = sf[idx + 1];
            vp[j] = fmaf(cw, f1 - f0, f0);
        }
        __stcs(&op[(size_t)tw * (PLANE / 4)], v);
    }
}

// ---------------------------------------------------------------------------
extern "C" void kernel_launch(void* const* d_in, const int* in_sizes, int n_in,
                              void* d_out, int out_size)
{
    const float* beta = nullptr;
    const float* toff = nullptr;
    const float* coff = nullptr;
    const float* tim  = nullptr;
    for (int i = 0; i < n_in; ++i) {
        switch (in_sizes[i]) {
            case NFACT * TT:                      beta = (const float*)d_in[i]; break;
            case NTRIALS * NCONFIGS * 2 * NFACT:  toff = (const float*)d_in[i]; break;
            case NCONFIGS * 2 * NFACT:            coff = (const float*)d_in[i]; break;
            case TT:                              tim  = (const float*)d_in[i]; break;
            default: break;
        }
    }
    float* out = (float*)d_out;

    fused_kernel<<<NGRP * GRP, 256>>>(beta, toff, coff, tim, out);
}

// round 10
// speedup vs baseline: 1.0511x; 1.0511x over previous
#include <cuda_runtime.h>
#include <math.h>

#define P_L1 20
#define P_R1 70
#define P_L2 120
#define P_R2 170
#define NFACT 10
#define TT 200
#define NTRIALS 256
#define NCONFIGS 128
#define TWN 50
#define WIN 53                        // softplus window [L-1, R+1]
#define PLANE (NTRIALS * NCONFIGS)    // 32768

#define N_FILL 4000                   // 1000 planes * 4 quarter-planes
#define N_WARP 5120                   // 20 k * 256 trials
#define GRP 16                        // 7 fill + 9 warp per group
#define NGRP 576

// JAX softplus: max(x,0) + log1p(exp(-|x|))
__device__ __forceinline__ float softplus_f(float x) {
    return fmaxf(x, 0.0f) + log1pf(expf(-fabsf(x)));
}

__global__ void __launch_bounds__(128) fused_kernel(
    const float* __restrict__ beta,
    const float* __restrict__ toff,    // [256,128,20]
    const float* __restrict__ coff,    // [128,20]
    const float* __restrict__ timev,   // [200]
    float* __restrict__ out)
{
    const int bid = blockIdx.x;
    const int grp = bid >> 4;
    const int sub = bid & 15;

    if (sub < 7) {
        // ---------------- fill path: quarter-plane broadcast ----------------
        int fid = grp * 7 + sub;           // 0..4031, valid 0..3999
        if (fid >= N_FILL) return;
        int p    = fid >> 2;               // plane 0..999 = (l, static col j)
        int quad = fid & 3;
        int l = p / 100;
        int j = p - l * 100;
        int t = (j < P_L1) ? j : ((j < 70) ? j + 50 : j + 100);

        float v = softplus_f(beta[l * TT + t]);
        float4 v4 = make_float4(v, v, v, v);

        float4* op = (float4*)(out + (size_t)(l * TT + t) * PLANE)
                   + quad * (PLANE / 16);
        #pragma unroll 4
        for (int i = threadIdx.x; i < PLANE / 16; i += 128)  // 2048 float4
            __stcs(&op[i], v4);
        return;
    }

    // ------------------- warp path --------------------------------------
    const int wid = grp * 9 + (sub - 7);   // 0..5183, valid 0..5119
    if (wid >= N_WARP) return;
    const int k   = wid >> 8;              // 0..19 (seg*10 + l)
    const int n   = wid & 255;             // trial
    const int seg = (k >= NFACT) ? 1 : 0;
    const int l   = k - seg * NFACT;
    const int Ls  = seg ? P_L2 : P_L1;
    const int Rs  = seg ? P_R2 : P_R1;

    const int tid  = threadIdx.x;
    const int lane = tid & 31;
    const int q    = tid >> 5;             // tw phase 0..3
    const int c0   = lane * 4;             // 4 consecutive configs per thread

    __shared__ float sf[WIN];

    if (tid < WIN)
        sf[tid] = softplus_f(beta[l * TT + (Ls - 1) + tid]);
    __syncthreads();

    // warp-parallel first-max argmax over sf[1..50] (each warp redundantly)
    float peak;
    {
        float bv = sf[1 + lane];
        int   bi = lane;                   // lanes cover elems 0..31
        if (lane < 18) {                   // elems 32..49
            float v2 = sf[33 + lane];
            if (v2 > bv) { bv = v2; bi = lane + 32; }
        }
        #pragma unroll
        for (int off = 16; off > 0; off >>= 1) {
            float ov = __shfl_xor_sync(0xffffffffu, bv, off);
            int   oi = __shfl_xor_sync(0xffffffffu, bi, off);
            if (ov > bv || (ov == bv && oi < bi)) { bv = ov; bi = oi; }
        }
        peak = timev[Ls + bi];
    }

    const float dt    = timev[1] - timev[0];
    const float rdt   = 1.0f / dt;
    const float ll    = timev[Ls];
    const float rl    = timev[Rs];
    const float shift = (float)(Ls - 1);
    const float b1s   = ll * rdt - shift;  // shifted left-branch intercept

    // per-config warp params (index-space affine pieces, pre-shifted)
    float t0[4], a1[4], a2[4], b2s[4];
    #pragma unroll
    for (int j = 0; j < 4; ++j) {
        int c = c0 + j;
        float s = peak + toff[(n * NCONFIGS + c) * (2 * NFACT) + k]
                       + coff[c * (2 * NFACT) + k];
        if (s <= ll) s = ll + dt;
        if (s >= rl) s = rl - dt;
        float lsp    = s - ll;
        float lslope = (peak - ll) / lsp;
        float rslope = (peak - rl) / (s - rl);
        t0[j]  = lsp * rdt;                         // branch point in tw units
        a1[j]  = lslope;
        a2[j]  = rslope;
        b2s[j] = (peak - lsp * rslope) * rdt - shift;
    }

    // base float4 pointer at (l, Ls, n, c0)
    float4* op = (float4*)(out + ((size_t)(l * TT + Ls) * NTRIALS + n) * NCONFIGS + c0);

    #pragma unroll 1
    for (int tw = q; tw < TWN; tw += 4) {
        float twf = (float)tw;
        float4 v;
        float* vp = (float*)&v;
        #pragma unroll
        for (int j = 0; j < 4; ++j) {
            // shifted index-space warp: wis = wi - (Ls-1), exact in fp32
            float wis = (twf < t0[j]) ? fmaf(twf, a1[j], b1s)
                                      : fmaf(twf, a2[j], b2s[j]);
            float fl = floorf(wis);
            float cw = wis - fl;
            int idx = (int)fl;             // proven 0 <= idx <= 51 (validated R9)
            float f0 = sf[idx];
            float f1 = sf[idx + 1];
            vp[j] = fmaf(cw, f1 - f0, f0);
        }
        __stcs(&op[(size_t)tw * (PLANE / 4)], v);
    }
}

// ---------------------------------------------------------------------------
extern "C" void kernel_launch(void* const* d_in, const int* in_sizes, int n_in,
                              void* d_out, int out_size)
{
    const float* beta = nullptr;
    const float* toff = nullptr;
    const float* coff = nullptr;
    const float* tim  = nullptr;
    for (int i = 0; i < n_in; ++i) {
        switch (in_sizes[i]) {
            case NFACT * TT:                      beta = (const float*)d_in[i]; break;
            case NTRIALS * NCONFIGS * 2 * NFACT:  toff = (const float*)d_in[i]; break;
            case NCONFIGS * 2 * NFACT:            coff = (const float*)d_in[i]; break;
            case TT:                              tim  = (const float*)d_in[i]; break;
            default: break;
        }
    }
    float* out = (float*)d_out;

    fused_kernel<<<NGRP * GRP, 128>>>(beta, toff, coff, tim, out);
}